// round 6
// baseline (speedup 1.0000x reference)
#include <cuda_runtime.h>
#include <math.h>

// Problem constants
#define B_  256
#define S_  256
#define H_  512
#define H2_ 1024
#define O_  512

// ---------------------------------------------------------------------------
// Scratch (device globals)
// ---------------------------------------------------------------------------
__device__ float g_xe  [(size_t)S_ * B_ * H_ ];
__device__ float g_Gx  [(size_t)S_ * B_ * H2_];
__device__ float g_Cx  [(size_t)S_ * B_ * H_ ];
__device__ float g_hall[(size_t)S_ * B_ * H_ ];
__device__ float g_h   [B_ * H_];
__device__ float g_z   [B_ * H_];
__device__ float g_rh  [B_ * H_];

__device__ unsigned g_cnt = 0;   // barrier arrival count (REDG target)
__device__ unsigned g_gen = 0;   // barrier generation

// ---------------------------------------------------------------------------
// f32x2 packed math helpers
// ---------------------------------------------------------------------------
typedef unsigned long long ull;

#define FMA2(d, a, b) \
    asm("fma.rn.f32x2 %0, %1, %2, %3;" : "=l"(d) : "l"(a), "l"(b), "l"(d))

__device__ __forceinline__ ull splat2(float x) {
    ull d;
    asm("mov.b64 %0, {%1, %1};" : "=l"(d) : "r"(__float_as_uint(x)));
    return d;
}
__device__ __forceinline__ float2 unpack2(ull v) {
    float2 r;
    asm("mov.b64 {%0, %1}, %2;" : "=f"(r.x), "=f"(r.y) : "l"(v));
    return r;
}

__device__ __forceinline__ float sigm(float x) {
    return __fdividef(1.0f, 1.0f + __expf(-x));
}
__device__ __forceinline__ float tanh_fast(float x) {
    return 1.0f - 2.0f * __fdividef(1.0f, __expf(2.0f * x) + 1.0f);
}

// ---------------------------------------------------------------------------
// Grid barrier: REDG arrival, single detector (block 0), one release word.
// ---------------------------------------------------------------------------
#define NBLK 256

__device__ __forceinline__ void grid_sync_red(unsigned next_gen) {
    __threadfence();
    __syncthreads();
    if (threadIdx.x == 0) {
        asm volatile("red.global.gpu.add.u32 [%0], %1;"
                     :: "l"(&g_cnt), "r"(1u) : "memory");
        if (blockIdx.x == 0) {
            while (atomicAdd(&g_cnt, 0u) < (unsigned)NBLK) { }
            *(volatile unsigned*)&g_cnt = 0u;
            __threadfence();
            *(volatile unsigned*)&g_gen = next_gen;
        } else {
            while (*(volatile unsigned*)&g_gen < next_gen) { }
        }
    }
    __syncthreads();
}

// ---------------------------------------------------------------------------
// Big SGEMM (proven): C[M,N] = A[M,512] @ Bw[N,512]^T + bias
// ---------------------------------------------------------------------------
#define TBM 128
#define TBN 128
#define TBK 16
#define LDT 132

__global__ __launch_bounds__(256, 2)
void sgemm_big(int Asel, const float* __restrict__ Bw, int ldb,
               const float* __restrict__ bias, int mode,
               float* __restrict__ yout) {
    __shared__ float As[TBK * LDT];
    __shared__ float Bs[TBK * LDT];

    const int tid = threadIdx.x;
    const int ty  = tid >> 4;
    const int tx  = tid & 15;
    const int m0  = blockIdx.y * TBM;
    const int n0  = blockIdx.x * TBN;

    const float* A = Asel ? g_hall : g_xe;

    ull acc[4][8];
    #pragma unroll
    for (int i = 0; i < 4; i++)
        #pragma unroll
        for (int j = 0; j < 8; j++) acc[i][j] = 0ull;

    for (int k0 = 0; k0 < H_; k0 += TBK) {
        #pragma unroll
        for (int it = 0; it < 2; it++) {
            int idx = tid + it * 256;
            int r   = idx >> 2;
            int kq  = idx & 3;
            float4 av = *(const float4*)(A  + (size_t)(m0 + r) * H_ + k0 + kq * 4);
            float4 bv = *(const float4*)(Bw + (size_t)(n0 + r) * ldb + k0 + kq * 4);
            As[(kq * 4 + 0) * LDT + r] = av.x;
            As[(kq * 4 + 1) * LDT + r] = av.y;
            As[(kq * 4 + 2) * LDT + r] = av.z;
            As[(kq * 4 + 3) * LDT + r] = av.w;
            Bs[(kq * 4 + 0) * LDT + r] = bv.x;
            Bs[(kq * 4 + 1) * LDT + r] = bv.y;
            Bs[(kq * 4 + 2) * LDT + r] = bv.z;
            Bs[(kq * 4 + 3) * LDT + r] = bv.w;
        }
        __syncthreads();

        #pragma unroll
        for (int kk = 0; kk < TBK; kk++) {
            ulonglong2 a01 = *(const ulonglong2*)&As[kk * LDT + ty * 8];
            ulonglong2 a23 = *(const ulonglong2*)&As[kk * LDT + ty * 8 + 4];
            float4 bl  = *(const float4*)&Bs[kk * LDT + tx * 8];
            float4 bh4 = *(const float4*)&Bs[kk * LDT + tx * 8 + 4];
            ull ap[4] = {a01.x, a01.y, a23.x, a23.y};
            float bsc[8] = {bl.x, bl.y, bl.z, bl.w, bh4.x, bh4.y, bh4.z, bh4.w};
            #pragma unroll
            for (int j = 0; j < 8; j++) {
                ull bb = splat2(bsc[j]);
                #pragma unroll
                for (int i = 0; i < 4; i++) FMA2(acc[i][j], ap[i], bb);
            }
        }
        __syncthreads();
    }

    #pragma unroll
    for (int i = 0; i < 4; i++) {
        #pragma unroll
        for (int j = 0; j < 8; j++) {
            float2 v = unpack2(acc[i][j]);
            int n  = n0 + tx * 8 + j;
            float bval = bias[n];
            int mA = m0 + ty * 8 + i * 2;
            int mB = mA + 1;
            float oA = v.x + bval, oB = v.y + bval;
            if (mode == 0) {
                g_Gx[(size_t)mA * H2_ + n] = oA;
                g_Gx[(size_t)mB * H2_ + n] = oB;
            } else if (mode == 1) {
                g_Cx[(size_t)mA * H_ + n] = oA;
                g_Cx[(size_t)mB * H_ + n] = oB;
            } else {
                int sA = mA >> 8, bA = mA & 255;
                int sB = mB >> 8, bB = mB & 255;
                yout[((size_t)bA * S_ + sA) * O_ + n] = oA;
                yout[((size_t)bB * S_ + sB) * O_ + n] = oB;
            }
        }
    }
}

// ---------------------------------------------------------------------------
// Persistent recurrent kernel: 256 blocks x 256 threads, 2 CTAs/SM.
// Block (mt=bid>>5, nt=bid&31):
//   gate tile:  m [mt*32,+32), n [nt*32,+32) of 1024; per-thread 1m x 4n
//   cand tile:  m [mt*32,+32), n [nt*16,+16) of 512;  per-thread 1m x 2n
// Weights in smem k-major: Wgs [512][32], Whs [512][16].
// Activation panel in smem [m][k] (LD 68), 64-k chunks, double-buffered;
// panel fills are direct STS.128, a-operand reads amortize 4 k per LDS.128.
// ---------------------------------------------------------------------------
#define WGS_OFF 0
#define WHS_OFF (512 * 32)                 // 16384 floats
#define AP_OFF  (WHS_OFF + 512 * 16)       // 24576 floats
#define APL2    68                          // panel row LD ([m][k] layout)
#define AP_BUF  (32 * APL2)                 // 2176 floats
#define PERSIST_SMEM ((AP_OFF + 2 * AP_BUF) * 4)   // 115712 bytes

__global__ __launch_bounds__(256, 2)
void gru_persist(const float* __restrict__ Wg, const float* __restrict__ Wh) {
    extern __shared__ float sm[];
    float* Wgs = sm + WGS_OFF;
    float* Whs = sm + WHS_OFF;
    float* AP  = sm + AP_OFF;

    const int tid = threadIdx.x;
    const int bid = blockIdx.x;
    const int mt  = bid >> 5;      // 0..7   (32-row m tile)
    const int nt  = bid & 31;      // 0..31
    const int ty  = tid >> 3;      // 0..31  -> m row (both phases)
    const int tx  = tid & 7;       // 0..7

    // init: zero h (first 32768 float4 across grid), load weight slices
    {
        int gid = bid * 256 + tid;
        if (gid < (B_ * H_) / 4)
            *(float4*)&g_h[gid * 4] = make_float4(0.f, 0.f, 0.f, 0.f);
    }
    for (int idx = tid; idx < 32 * 128; idx += 256) {   // Wgs: 32 cols x 128 f4
        int j  = idx >> 7;
        int k4 = idx & 127;
        float4 v = *(const float4*)(Wg + (size_t)(nt * 32 + j) * H2_ + H_ + k4 * 4);
        Wgs[(k4 * 4 + 0) * 32 + j] = v.x;
        Wgs[(k4 * 4 + 1) * 32 + j] = v.y;
        Wgs[(k4 * 4 + 2) * 32 + j] = v.z;
        Wgs[(k4 * 4 + 3) * 32 + j] = v.w;
    }
    for (int idx = tid; idx < 16 * 128; idx += 256) {   // Whs: 16 cols x 128 f4
        int j  = idx >> 7;
        int k4 = idx & 127;
        float4 v = *(const float4*)(Wh + (size_t)(nt * 16 + j) * H2_ + H_ + k4 * 4);
        Whs[(k4 * 4 + 0) * 16 + j] = v.x;
        Whs[(k4 * 4 + 1) * 16 + j] = v.y;
        Whs[(k4 * 4 + 2) * 16 + j] = v.z;
        Whs[(k4 * 4 + 3) * 16 + j] = v.w;
    }
    unsigned gen = 0;
    grid_sync_red(++gen);

    const float* hrow  = g_h  + (size_t)mt * 32 * H_;
    const float* rhrow = g_rh + (size_t)mt * 32 * H_;

    // panel-fill coords: two float4 per thread per 64-k chunk
    const int pm0 = tid >> 4;            // 0..15
    const int pk0 = (tid & 15) * 4;      // 0..60
    const int pm1 = pm0 + 16;            // 16..31

    const int mg  = mt * 32 + ty;        // this thread's output m row
    const int ngt = nt * 32 + tx * 4;    // gate n base (4 cols)
    const int nct = nt * 16 + tx * 2;    // cand n base (2 cols)

    for (int t = 0; t < S_; t++) {
        // ===================== GATE PHASE =====================
        float4 pf0 = __ldcg((const float4*)(hrow + (size_t)pm0 * H_ + pk0));
        float4 pf1 = __ldcg((const float4*)(hrow + (size_t)pm1 * H_ + pk0));
        const float* Gxt = g_Gx + (size_t)t * B_ * H2_;
        float4 gx = __ldcg((const float4*)(Gxt + (size_t)mg * H2_ + ngt));
        float4 hv = make_float4(0.f, 0.f, 0.f, 0.f);
        if (nt >= 16)
            hv = __ldcg((const float4*)(g_h + mg * H_ + (ngt - H_)));

        ull acc0 = 0ull, acc1 = 0ull;
        #pragma unroll 1
        for (int c = 0; c < 8; c++) {
            float* buf = AP + (c & 1) * AP_BUF;
            *(float4*)(buf + pm0 * APL2 + pk0) = pf0;
            *(float4*)(buf + pm1 * APL2 + pk0) = pf1;
            __syncthreads();
            if (c < 7) {
                int ko = (c + 1) * 64 + pk0;
                pf0 = __ldcg((const float4*)(hrow + (size_t)pm0 * H_ + ko));
                pf1 = __ldcg((const float4*)(hrow + (size_t)pm1 * H_ + ko));
            }
            const float* ar = buf + ty * APL2;
            const float* wb = Wgs + (size_t)c * 64 * 32 + tx * 4;
            #pragma unroll
            for (int k4 = 0; k4 < 16; k4++) {
                float4 a4 = *(const float4*)(ar + k4 * 4);
                ulonglong2 b0 = *(const ulonglong2*)(wb + (k4 * 4 + 0) * 32);
                ulonglong2 b1 = *(const ulonglong2*)(wb + (k4 * 4 + 1) * 32);
                ulonglong2 b2 = *(const ulonglong2*)(wb + (k4 * 4 + 2) * 32);
                ulonglong2 b3 = *(const ulonglong2*)(wb + (k4 * 4 + 3) * 32);
                ull s;
                s = splat2(a4.x); FMA2(acc0, s, b0.x); FMA2(acc1, s, b0.y);
                s = splat2(a4.y); FMA2(acc0, s, b1.x); FMA2(acc1, s, b1.y);
                s = splat2(a4.z); FMA2(acc0, s, b2.x); FMA2(acc1, s, b2.y);
                s = splat2(a4.w); FMA2(acc0, s, b3.x); FMA2(acc1, s, b3.y);
            }
        }
        // gate epilogue
        {
            float2 v0 = unpack2(acc0), v1 = unpack2(acc1);
            float4 r = make_float4(sigm(v0.x + gx.x), sigm(v0.y + gx.y),
                                   sigm(v1.x + gx.z), sigm(v1.y + gx.w));
            if (nt < 16) {
                __stcg((float4*)(g_z + mg * H_ + ngt), r);
            } else {
                r.x *= hv.x; r.y *= hv.y; r.z *= hv.z; r.w *= hv.w;
                __stcg((float4*)(g_rh + mg * H_ + (ngt - H_)), r);
            }
        }
        grid_sync_red(++gen);

        // ===================== CANDIDATE PHASE =====================
        float4 qf0 = __ldcg((const float4*)(rhrow + (size_t)pm0 * H_ + pk0));
        float4 qf1 = __ldcg((const float4*)(rhrow + (size_t)pm1 * H_ + pk0));
        const float* Cxt = g_Cx + (size_t)t * B_ * H_;
        float2 cx = __ldcg((const float2*)(Cxt + (size_t)mg * H_ + nct));
        float2 zz = __ldcg((const float2*)(g_z + mg * H_ + nct));
        float2 hh = __ldcg((const float2*)(g_h + mg * H_ + nct));

        ull cacc = 0ull;
        #pragma unroll 1
        for (int c = 0; c < 8; c++) {
            float* buf = AP + (c & 1) * AP_BUF;
            *(float4*)(buf + pm0 * APL2 + pk0) = qf0;
            *(float4*)(buf + pm1 * APL2 + pk0) = qf1;
            __syncthreads();
            if (c < 7) {
                int ko = (c + 1) * 64 + pk0;
                qf0 = __ldcg((const float4*)(rhrow + (size_t)pm0 * H_ + ko));
                qf1 = __ldcg((const float4*)(rhrow + (size_t)pm1 * H_ + ko));
            }
            const float* ar = buf + ty * APL2;
            const float* wb = Whs + (size_t)c * 64 * 16 + tx * 2;
            #pragma unroll
            for (int k4 = 0; k4 < 16; k4++) {
                float4 a4 = *(const float4*)(ar + k4 * 4);
                ull b0 = *(const ull*)(wb + (k4 * 4 + 0) * 16);
                ull b1 = *(const ull*)(wb + (k4 * 4 + 1) * 16);
                ull b2 = *(const ull*)(wb + (k4 * 4 + 2) * 16);
                ull b3 = *(const ull*)(wb + (k4 * 4 + 3) * 16);
                FMA2(cacc, splat2(a4.x), b0);
                FMA2(cacc, splat2(a4.y), b1);
                FMA2(cacc, splat2(a4.z), b2);
                FMA2(cacc, splat2(a4.w), b3);
            }
        }
        // candidate epilogue: h update
        {
            float* hall_t = g_hall + (size_t)t * B_ * H_;
            float2 v = unpack2(cacc);
            float c0 = tanh_fast(v.x + cx.x);
            float c1 = tanh_fast(v.y + cx.y);
            float h0 = fmaf(zz.x, c0 - hh.x, hh.x);
            float h1 = fmaf(zz.y, c1 - hh.y, hh.y);
            float2 w = make_float2(h0, h1);
            __stcg((float2*)(g_h + mg * H_ + nct), w);
            __stcg((float2*)(hall_t + (size_t)mg * H_ + nct), w);
        }
        grid_sync_red(++gen);
    }
}

// ---------------------------------------------------------------------------
__global__ void gather_embed(const int* __restrict__ x,
                             const float* __restrict__ emb) {
    if (blockIdx.x == 0 && threadIdx.x == 0) {
        g_cnt = 0;                 // reset barrier state each launch
        g_gen = 0;
    }
    int idx = blockIdx.x * 256 + threadIdx.x;
    int h4  = idx & (H_ / 4 - 1);
    int row = idx >> 7;
    int b   = row & (B_ - 1);
    int s   = row >> 8;
    int tok = x[b * S_ + s];
    reinterpret_cast<float4*>(g_xe)[(size_t)row * (H_ / 4) + h4] =
        reinterpret_cast<const float4*>(emb)[(size_t)tok * (H_ / 4) + h4];
}

__global__ void copy_hfinal(float* __restrict__ out) {
    int i = blockIdx.x * 256 + threadIdx.x;
    out[i] = g_h[i];
}

// ---------------------------------------------------------------------------
extern "C" void kernel_launch(void* const* d_in, const int* in_sizes, int n_in,
                              void* d_out, int out_size) {
    (void)in_sizes; (void)n_in; (void)out_size;
    const int*   x   = (const int*)  d_in[0];
    const float* emb = (const float*)d_in[1];
    const float* Wg  = (const float*)d_in[2];
    const float* bg  = (const float*)d_in[3];
    const float* Wh  = (const float*)d_in[4];
    const float* bh  = (const float*)d_in[5];
    const float* Wo  = (const float*)d_in[6];
    const float* bo  = (const float*)d_in[7];
    float* out = (float*)d_out;

    static int smem_set = 0;
    if (!smem_set) {
        cudaFuncSetAttribute(gru_persist,
                             cudaFuncAttributeMaxDynamicSharedMemorySize,
                             PERSIST_SMEM);
        smem_set = 1;
    }

    gather_embed<<<(S_ * B_ * (H_ / 4)) / 256, 256>>>(x, emb);

    sgemm_big<<<dim3(H2_ / TBN, (S_ * B_) / TBM), 256>>>(0, Wg, H2_, bg, 0, nullptr);
    sgemm_big<<<dim3(H_  / TBN, (S_ * B_) / TBM), 256>>>(0, Wh, H2_, bh, 1, nullptr);

    gru_persist<<<NBLK, 256, PERSIST_SMEM>>>(Wg, Wh);

    sgemm_big<<<dim3(O_ / TBN, (S_ * B_) / TBM), 256>>>(1, Wo, H_, bo, 2,
                                                        out + (size_t)B_ * H_);
    copy_hfinal<<<(B_ * H_) / 256, 256>>>(out);
}

// round 7
// speedup vs baseline: 1.3641x; 1.3641x over previous
#include <cuda_runtime.h>
#include <math.h>

// Problem constants
#define B_  256
#define S_  256
#define H_  512
#define H2_ 1024
#define O_  512

// ---------------------------------------------------------------------------
// Scratch (device globals)
// ---------------------------------------------------------------------------
__device__ float g_xe  [(size_t)S_ * B_ * H_ ];
__device__ float g_Gx  [(size_t)S_ * B_ * H2_];
__device__ float g_Cx  [(size_t)S_ * B_ * H_ ];
__device__ float g_hall[(size_t)S_ * B_ * H_ ];
__device__ float g_h   [B_ * H_];
__device__ float g_z   [B_ * H_];
__device__ float g_rh  [B_ * H_];

// Per-group barrier counters (8 groups, padded to 128B apart)
__device__ unsigned g_gcnt[8 * 32];

// ---------------------------------------------------------------------------
// f32x2 packed math helpers
// ---------------------------------------------------------------------------
typedef unsigned long long ull;

#define FMA2(d, a, b) \
    asm("fma.rn.f32x2 %0, %1, %2, %3;" : "=l"(d) : "l"(a), "l"(b), "l"(d))

__device__ __forceinline__ ull splat2(float x) {
    ull d;
    asm("mov.b64 %0, {%1, %1};" : "=l"(d) : "r"(__float_as_uint(x)));
    return d;
}
__device__ __forceinline__ float2 unpack2(ull v) {
    float2 r;
    asm("mov.b64 {%0, %1}, %2;" : "=f"(r.x), "=f"(r.y) : "l"(v));
    return r;
}

__device__ __forceinline__ float sigm(float x) {
    return __fdividef(1.0f, 1.0f + __expf(-x));
}
__device__ __forceinline__ float tanh_fast(float x) {
    return 1.0f - 2.0f * __fdividef(1.0f, __expf(2.0f * x) + 1.0f);
}

// ---------------------------------------------------------------------------
// Group barrier (16 blocks per group): REDG arrival on the group's counter,
// leaderless monotonic-count wait (count >= 16*gen). No reset, no race.
// g_gcnt is zeroed by gather_embed each launch.
// ---------------------------------------------------------------------------
__device__ __forceinline__ void group_sync(int grp, unsigned target) {
    __threadfence();
    __syncthreads();
    if (threadIdx.x == 0) {
        unsigned* cp = &g_gcnt[grp * 32];
        asm volatile("red.global.gpu.add.u32 [%0], %1;"
                     :: "l"(cp), "r"(1u) : "memory");
        unsigned v;
        do {
            asm volatile("ld.acquire.gpu.u32 %0, [%1];" : "=r"(v) : "l"(cp));
        } while (v < target);
    }
    __syncthreads();
}

// ---------------------------------------------------------------------------
// Big SGEMM (proven): C[M,N] = A[M,512] @ Bw[N,512]^T + bias
// ---------------------------------------------------------------------------
#define TBM 128
#define TBN 128
#define TBK 16
#define LDT 132

__global__ __launch_bounds__(256, 2)
void sgemm_big(int Asel, const float* __restrict__ Bw, int ldb,
               const float* __restrict__ bias, int mode,
               float* __restrict__ yout) {
    __shared__ float As[TBK * LDT];
    __shared__ float Bs[TBK * LDT];

    const int tid = threadIdx.x;
    const int ty  = tid >> 4;
    const int tx  = tid & 15;
    const int m0  = blockIdx.y * TBM;
    const int n0  = blockIdx.x * TBN;

    const float* A = Asel ? g_hall : g_xe;

    ull acc[4][8];
    #pragma unroll
    for (int i = 0; i < 4; i++)
        #pragma unroll
        for (int j = 0; j < 8; j++) acc[i][j] = 0ull;

    for (int k0 = 0; k0 < H_; k0 += TBK) {
        #pragma unroll
        for (int it = 0; it < 2; it++) {
            int idx = tid + it * 256;
            int r   = idx >> 2;
            int kq  = idx & 3;
            float4 av = *(const float4*)(A  + (size_t)(m0 + r) * H_ + k0 + kq * 4);
            float4 bv = *(const float4*)(Bw + (size_t)(n0 + r) * ldb + k0 + kq * 4);
            As[(kq * 4 + 0) * LDT + r] = av.x;
            As[(kq * 4 + 1) * LDT + r] = av.y;
            As[(kq * 4 + 2) * LDT + r] = av.z;
            As[(kq * 4 + 3) * LDT + r] = av.w;
            Bs[(kq * 4 + 0) * LDT + r] = bv.x;
            Bs[(kq * 4 + 1) * LDT + r] = bv.y;
            Bs[(kq * 4 + 2) * LDT + r] = bv.z;
            Bs[(kq * 4 + 3) * LDT + r] = bv.w;
        }
        __syncthreads();

        #pragma unroll
        for (int kk = 0; kk < TBK; kk++) {
            ulonglong2 a01 = *(const ulonglong2*)&As[kk * LDT + ty * 8];
            ulonglong2 a23 = *(const ulonglong2*)&As[kk * LDT + ty * 8 + 4];
            float4 bl  = *(const float4*)&Bs[kk * LDT + tx * 8];
            float4 bh4 = *(const float4*)&Bs[kk * LDT + tx * 8 + 4];
            ull ap[4] = {a01.x, a01.y, a23.x, a23.y};
            float bsc[8] = {bl.x, bl.y, bl.z, bl.w, bh4.x, bh4.y, bh4.z, bh4.w};
            #pragma unroll
            for (int j = 0; j < 8; j++) {
                ull bb = splat2(bsc[j]);
                #pragma unroll
                for (int i = 0; i < 4; i++) FMA2(acc[i][j], ap[i], bb);
            }
        }
        __syncthreads();
    }

    #pragma unroll
    for (int i = 0; i < 4; i++) {
        #pragma unroll
        for (int j = 0; j < 8; j++) {
            float2 v = unpack2(acc[i][j]);
            int n  = n0 + tx * 8 + j;
            float bval = bias[n];
            int mA = m0 + ty * 8 + i * 2;
            int mB = mA + 1;
            float oA = v.x + bval, oB = v.y + bval;
            if (mode == 0) {
                g_Gx[(size_t)mA * H2_ + n] = oA;
                g_Gx[(size_t)mB * H2_ + n] = oB;
            } else if (mode == 1) {
                g_Cx[(size_t)mA * H_ + n] = oA;
                g_Cx[(size_t)mB * H_ + n] = oB;
            } else {
                int sA = mA >> 8, bA = mA & 255;
                int sB = mB >> 8, bB = mB & 255;
                yout[((size_t)bA * S_ + sA) * O_ + n] = oA;
                yout[((size_t)bB * S_ + sB) * O_ + n] = oB;
            }
        }
    }
}

// ---------------------------------------------------------------------------
// Persistent recurrent kernel (R3 structure), 128 blocks x 256 threads.
// Block (mt=bid>>4, nt=bid&15):
//   gate tile:  m [mt*32,+32), n [nt*64,+64) of 1024; thread tile 2m x 4n
//   cand tile:  m [mt*32,+32), n [nt*32,+32) of 512;  thread tile 2m x 2n
// ALL cross-block dataflow is within the 16-block mt-group, so barriers are
// group-scoped (16 arrivals), decoupling the 8 groups from each other.
// ---------------------------------------------------------------------------
#define WGS_LD 64
#define WHS_LD 32
#define APL    34
#define WGS_OFF 0
#define WHS_OFF (512 * WGS_LD)             // 32768 floats
#define AP_OFF  (WHS_OFF + 512 * WHS_LD)   // 49152 floats
#define AP_BUF  (64 * APL)                 // 2176 floats
#define PERSIST_SMEM ((AP_OFF + 2 * AP_BUF) * 4)   // 214016 bytes

__global__ __launch_bounds__(256, 1)
void gru_persist(const float* __restrict__ Wg, const float* __restrict__ Wh) {
    extern __shared__ float sm[];
    float* Wgs = sm + WGS_OFF;
    float* Whs = sm + WHS_OFF;
    float* AP  = sm + AP_OFF;

    const int tid = threadIdx.x;
    const int bid = blockIdx.x;
    const int mt  = bid >> 4;
    const int nt  = bid & 15;
    const int ty  = tid >> 4;      // m-pair index: rows ty*2, ty*2+1
    const int tx  = tid & 15;

    // init: zero h (block bid zeroes rows bid*2..+2 -> group-local coverage)
    {
        int base = (bid * 256 + tid) * 4;
        *(float4*)&g_h[base] = make_float4(0.f, 0.f, 0.f, 0.f);
    }
    for (int idx = tid; idx < 64 * 128; idx += 256) {
        int j  = idx >> 7;
        int k4 = idx & 127;
        float4 v = *(const float4*)(Wg + (size_t)(nt * 64 + j) * H2_ + H_ + k4 * 4);
        Wgs[(k4 * 4 + 0) * WGS_LD + j] = v.x;
        Wgs[(k4 * 4 + 1) * WGS_LD + j] = v.y;
        Wgs[(k4 * 4 + 2) * WGS_LD + j] = v.z;
        Wgs[(k4 * 4 + 3) * WGS_LD + j] = v.w;
    }
    for (int idx = tid; idx < 32 * 128; idx += 256) {
        int j  = idx >> 7;
        int k4 = idx & 127;
        float4 v = *(const float4*)(Wh + (size_t)(nt * 32 + j) * H2_ + H_ + k4 * 4);
        Whs[(k4 * 4 + 0) * WHS_LD + j] = v.x;
        Whs[(k4 * 4 + 1) * WHS_LD + j] = v.y;
        Whs[(k4 * 4 + 2) * WHS_LD + j] = v.z;
        Whs[(k4 * 4 + 3) * WHS_LD + j] = v.w;
    }
    unsigned tgt = 0;
    group_sync(mt, tgt += 16);

    const float* hrow  = g_h  + (size_t)mt * 32 * H_;
    const float* rhrow = g_rh + (size_t)mt * 32 * H_;

    // per-thread panel-load coords (two float4 loads per chunk)
    const int pm0 = tid >> 4;            // 0..15
    const int pk0 = (tid & 15) * 4;      // 0..60
    const int pm1 = pm0 + 16;            // 16..31
    const int m0g = mt * 32 + ty * 2;    // global m for this thread's outputs
    const int nbg = nt * 64 + tx * 4;    // gate n base
    const int nbc = nt * 32 + tx * 2;    // cand n base

    for (int t = 0; t < S_; t++) {
        // ===================== GATE PHASE =====================
        float4 pf0 = __ldcg((const float4*)(hrow + (size_t)pm0 * H_ + pk0));
        float4 pf1 = __ldcg((const float4*)(hrow + (size_t)pm1 * H_ + pk0));
        const float* Gxt = g_Gx + (size_t)t * B_ * H2_;
        float4 gx0 = __ldcg((const float4*)(Gxt + (size_t)m0g * H2_ + nbg));
        float4 gx1 = __ldcg((const float4*)(Gxt + (size_t)(m0g + 1) * H2_ + nbg));
        float4 hv0 = make_float4(0.f,0.f,0.f,0.f), hv1 = hv0;
        if (nt >= 8) {
            int n2 = nbg - H_;
            hv0 = __ldcg((const float4*)(g_h + m0g * H_ + n2));
            hv1 = __ldcg((const float4*)(g_h + (m0g + 1) * H_ + n2));
        }

        ull a00 = 0ull, a01 = 0ull, a10 = 0ull, a11 = 0ull;
        #pragma unroll 1
        for (int c = 0; c < 8; c++) {
            float* buf = AP + (c & 1) * AP_BUF;
            {
                int kq = pk0 >> 2;
                buf[(kq * 4 + 0) * APL + pm0] = pf0.x;
                buf[(kq * 4 + 1) * APL + pm0] = pf0.y;
                buf[(kq * 4 + 2) * APL + pm0] = pf0.z;
                buf[(kq * 4 + 3) * APL + pm0] = pf0.w;
                buf[(kq * 4 + 0) * APL + pm1] = pf1.x;
                buf[(kq * 4 + 1) * APL + pm1] = pf1.y;
                buf[(kq * 4 + 2) * APL + pm1] = pf1.z;
                buf[(kq * 4 + 3) * APL + pm1] = pf1.w;
            }
            __syncthreads();
            if (c < 7) {
                int ko = (c + 1) * 64 + pk0;
                pf0 = __ldcg((const float4*)(hrow + (size_t)pm0 * H_ + ko));
                pf1 = __ldcg((const float4*)(hrow + (size_t)pm1 * H_ + ko));
            }
            const float* wb = Wgs + (size_t)c * 64 * WGS_LD + tx * 4;
            const float* ab = buf + ty * 2;
            #pragma unroll 16
            for (int kk = 0; kk < 64; kk++) {
                float2 a = *(const float2*)(ab + kk * APL);
                ulonglong2 b = *(const ulonglong2*)(wb + kk * WGS_LD);
                ull s0 = splat2(a.x), s1 = splat2(a.y);
                FMA2(a00, s0, b.x); FMA2(a01, s0, b.y);
                FMA2(a10, s1, b.x); FMA2(a11, s1, b.y);
            }
        }
        // gate epilogue
        {
            float2 v00 = unpack2(a00), v01 = unpack2(a01);
            float2 v10 = unpack2(a10), v11 = unpack2(a11);
            float4 r0 = make_float4(sigm(v00.x + gx0.x), sigm(v00.y + gx0.y),
                                    sigm(v01.x + gx0.z), sigm(v01.y + gx0.w));
            float4 r1 = make_float4(sigm(v10.x + gx1.x), sigm(v10.y + gx1.y),
                                    sigm(v11.x + gx1.z), sigm(v11.y + gx1.w));
            if (nt < 8) {
                __stcg((float4*)(g_z + m0g * H_ + nbg), r0);
                __stcg((float4*)(g_z + (m0g + 1) * H_ + nbg), r1);
            } else {
                int n2 = nbg - H_;
                r0.x *= hv0.x; r0.y *= hv0.y; r0.z *= hv0.z; r0.w *= hv0.w;
                r1.x *= hv1.x; r1.y *= hv1.y; r1.z *= hv1.z; r1.w *= hv1.w;
                __stcg((float4*)(g_rh + m0g * H_ + n2), r0);
                __stcg((float4*)(g_rh + (m0g + 1) * H_ + n2), r1);
            }
        }
        group_sync(mt, tgt += 16);

        // ===================== CANDIDATE PHASE =====================
        float4 qf0 = __ldcg((const float4*)(rhrow + (size_t)pm0 * H_ + pk0));
        float4 qf1 = __ldcg((const float4*)(rhrow + (size_t)pm1 * H_ + pk0));
        const float* Cxt = g_Cx + (size_t)t * B_ * H_;
        float2 cx0 = __ldcg((const float2*)(Cxt + (size_t)m0g * H_ + nbc));
        float2 cx1 = __ldcg((const float2*)(Cxt + (size_t)(m0g + 1) * H_ + nbc));
        float2 zz0 = __ldcg((const float2*)(g_z + m0g * H_ + nbc));
        float2 zz1 = __ldcg((const float2*)(g_z + (m0g + 1) * H_ + nbc));
        float2 hh0 = __ldcg((const float2*)(g_h + m0g * H_ + nbc));
        float2 hh1 = __ldcg((const float2*)(g_h + (m0g + 1) * H_ + nbc));

        ull c0 = 0ull, c1 = 0ull;
        #pragma unroll 1
        for (int c = 0; c < 8; c++) {
            float* buf = AP + (c & 1) * AP_BUF;
            {
                int kq = pk0 >> 2;
                buf[(kq * 4 + 0) * APL + pm0] = qf0.x;
                buf[(kq * 4 + 1) * APL + pm0] = qf0.y;
                buf[(kq * 4 + 2) * APL + pm0] = qf0.z;
                buf[(kq * 4 + 3) * APL + pm0] = qf0.w;
                buf[(kq * 4 + 0) * APL + pm1] = qf1.x;
                buf[(kq * 4 + 1) * APL + pm1] = qf1.y;
                buf[(kq * 4 + 2) * APL + pm1] = qf1.z;
                buf[(kq * 4 + 3) * APL + pm1] = qf1.w;
            }
            __syncthreads();
            if (c < 7) {
                int ko = (c + 1) * 64 + pk0;
                qf0 = __ldcg((const float4*)(rhrow + (size_t)pm0 * H_ + ko));
                qf1 = __ldcg((const float4*)(rhrow + (size_t)pm1 * H_ + ko));
            }
            const float* wb = Whs + (size_t)c * 64 * WHS_LD + tx * 2;
            const float* ab = buf + ty * 2;
            #pragma unroll 16
            for (int kk = 0; kk < 64; kk++) {
                float2 a = *(const float2*)(ab + kk * APL);
                ull b = *(const ull*)(wb + kk * WHS_LD);
                FMA2(c0, splat2(a.x), b);
                FMA2(c1, splat2(a.y), b);
            }
        }
        // candidate epilogue: h update
        {
            float* hall_t = g_hall + (size_t)t * B_ * H_;
            float2 v0 = unpack2(c0), v1 = unpack2(c1);
            float cnd;
            cnd = tanh_fast(v0.x + cx0.x);
            float h00 = fmaf(zz0.x, cnd - hh0.x, hh0.x);
            cnd = tanh_fast(v0.y + cx0.y);
            float h01 = fmaf(zz0.y, cnd - hh0.y, hh0.y);
            cnd = tanh_fast(v1.x + cx1.x);
            float h10 = fmaf(zz1.x, cnd - hh1.x, hh1.x);
            cnd = tanh_fast(v1.y + cx1.y);
            float h11 = fmaf(zz1.y, cnd - hh1.y, hh1.y);
            float2 w0 = make_float2(h00, h01);
            float2 w1 = make_float2(h10, h11);
            __stcg((float2*)(g_h + m0g * H_ + nbc), w0);
            __stcg((float2*)(g_h + (m0g + 1) * H_ + nbc), w1);
            __stcg((float2*)(hall_t + (size_t)m0g * H_ + nbc), w0);
            __stcg((float2*)(hall_t + (size_t)(m0g + 1) * H_ + nbc), w1);
        }
        group_sync(mt, tgt += 16);
    }
}

// ---------------------------------------------------------------------------
__global__ void gather_embed(const int* __restrict__ x,
                             const float* __restrict__ emb) {
    if (blockIdx.x == 0 && threadIdx.x < 8 * 32)
        g_gcnt[threadIdx.x] = 0;   // reset group-barrier counters each launch
    int idx = blockIdx.x * 256 + threadIdx.x;
    int h4  = idx & (H_ / 4 - 1);
    int row = idx >> 7;
    int b   = row & (B_ - 1);
    int s   = row >> 8;
    int tok = x[b * S_ + s];
    reinterpret_cast<float4*>(g_xe)[(size_t)row * (H_ / 4) + h4] =
        reinterpret_cast<const float4*>(emb)[(size_t)tok * (H_ / 4) + h4];
}

__global__ void copy_hfinal(float* __restrict__ out) {
    int i = blockIdx.x * 256 + threadIdx.x;
    out[i] = g_h[i];
}

// ---------------------------------------------------------------------------
extern "C" void kernel_launch(void* const* d_in, const int* in_sizes, int n_in,
                              void* d_out, int out_size) {
    (void)in_sizes; (void)n_in; (void)out_size;
    const int*   x   = (const int*)  d_in[0];
    const float* emb = (const float*)d_in[1];
    const float* Wg  = (const float*)d_in[2];
    const float* bg  = (const float*)d_in[3];
    const float* Wh  = (const float*)d_in[4];
    const float* bh  = (const float*)d_in[5];
    const float* Wo  = (const float*)d_in[6];
    const float* bo  = (const float*)d_in[7];
    float* out = (float*)d_out;

    static int smem_set = 0;
    if (!smem_set) {
        cudaFuncSetAttribute(gru_persist,
                             cudaFuncAttributeMaxDynamicSharedMemorySize,
                             PERSIST_SMEM);
        smem_set = 1;
    }

    gather_embed<<<(S_ * B_ * (H_ / 4)) / 256, 256>>>(x, emb);

    sgemm_big<<<dim3(H2_ / TBN, (S_ * B_) / TBM), 256>>>(0, Wg, H2_, bg, 0, nullptr);
    sgemm_big<<<dim3(H_  / TBN, (S_ * B_) / TBM), 256>>>(0, Wh, H2_, bh, 1, nullptr);

    gru_persist<<<128, 256, PERSIST_SMEM>>>(Wg, Wh);

    sgemm_big<<<dim3(O_ / TBN, (S_ * B_) / TBM), 256>>>(1, Wo, H_, bo, 2,
                                                        out + (size_t)B_ * H_);
    copy_hfinal<<<(B_ * H_) / 256, 256>>>(out);
}